// round 15
// baseline (speedup 1.0000x reference)
#include <cuda_runtime.h>
#include <math.h>
#include <cstdint>

#define SEQL   2048
#define NHEAD  8
#define DMODEL 512
#define HDIM   64
#define CATD   128
#define NHTOT  16
#define XTOT   (4096 * DMODEL)     // one input tensor (N*L=4096 rows x 512)

// Scratch (allocation-free). All values stored pre-rounded to tf32 bit patterns.
__device__ float g_A [(size_t)NHTOT * SEQL * CATD];   // [nh][l][c]   attn A operand
__device__ float g_B [(size_t)NHTOT * SEQL * CATD];   // [nh][l][c]   attn B operand
__device__ float g_Vt[(size_t)NHTOT * HDIM * SEQL];   // [nh][d][l]   attn stage-2 B operand
__device__ float g_Xr[2 * XTOT];                      // tf32-rounded query | key
__device__ float g_Wr[3 * DMODEL * DMODEL];           // tf32-rounded Wq | Wk | Wv

#define DINL __device__ __forceinline__

DINL uint32_t f2tf(float f) {           // round fp32 -> tf32 (rna), fp32 bit layout
    uint32_t u;
    asm("cvt.rna.tf32.f32 %0, %1;" : "=r"(u) : "f"(f));
    return u;
}

// m16n8k8 tf32 MMA, fp32 accumulate (legacy mma.sync path, base sm_103 ISA)
DINL void mma8(float* d, const uint32_t* a, const uint32_t* b) {
    asm volatile("mma.sync.aligned.m16n8k8.row.col.f32.tf32.tf32.f32 "
        "{%0,%1,%2,%3}, {%4,%5,%6,%7}, {%8,%9}, {%0,%1,%2,%3};"
        : "+f"(d[0]), "+f"(d[1]), "+f"(d[2]), "+f"(d[3])
        : "r"(a[0]), "r"(a[1]), "r"(a[2]), "r"(a[3]), "r"(b[0]), "r"(b[1]));
}

// ldmatrix x4 (b16): 4 8x8 b16 matrices == one 16x8 b32 tile (validated R14).
DINL void ldsm4(uint32_t* r, uint32_t addr) {
    asm volatile("ldmatrix.sync.aligned.m8n8.x4.shared.b16 {%0,%1,%2,%3}, [%4];"
        : "=r"(r[0]), "=r"(r[1]), "=r"(r[2]), "=r"(r[3]) : "r"(addr));
}

DINL uint32_t smem_u32(const void* p) {
    uint32_t a;
    asm("{ .reg .u64 t; cvta.to.shared.u64 t, %1; cvt.u32.u64 %0, t; }" : "=r"(a) : "l"(p));
    return a;
}
DINL void cp16(uint32_t dst, const void* src) {
    asm volatile("cp.async.cg.shared.global [%0], [%1], 16;" :: "r"(dst), "l"(src));
}
#define CP_COMMIT() asm volatile("cp.async.commit_group;" ::: "memory")
#define CP_WAIT(N)  asm volatile("cp.async.wait_group %0;" :: "n"(N) : "memory")
#define CP_WAIT0()  asm volatile("cp.async.commit_group;\n\tcp.async.wait_group 0;" ::: "memory")

DINL float softplus_f(float x) {
    return fmaxf(x, 0.f) + log1pf(__expf(-fabsf(x)));
}
DINL void sincos_red(float ang, float* s, float* c) {
    const float INV2PI = 0.15915494309189535f;
    const float PI2_HI = 6.28318548202514648f;
    const float PI2_LO = -1.74845553e-7f;
    float k = rintf(ang * INV2PI);
    float r = fmaf(-k, PI2_HI, ang);
    r = fmaf(-k, PI2_LO, r);
    *s = __sinf(r);
    *c = __cosf(r);
}

// ldmatrix per-lane row/col mappings (validated bit-exact in R14)
DINL int ldsm_b_row(int lane) { return (lane & 7) + ((lane >> 4) << 3); }
DINL int ldsm_b_col(int lane) { return ((lane >> 3) & 1) << 2; }
DINL int ldsm_a_row(int lane) { return (lane & 7) + (((lane >> 3) & 1) << 3); }
DINL int ldsm_a_col(int lane) { return (lane >> 4) << 2; }

// ─────────────────────────── Prepass: tf32-round inputs into scratch ────────
__global__ __launch_bounds__(256) void prepass_tc(
    const float* __restrict__ query, const float* __restrict__ key,
    const float* __restrict__ Wq, const float* __restrict__ Wk, const float* __restrict__ Wv)
{
    int sel = blockIdx.y;
    const float4* src;
    float4* dst;
    int cnt;
    if (sel == 0)      { src = (const float4*)query; dst = (float4*)g_Xr;          cnt = XTOT / 4; }
    else if (sel == 1) { src = (const float4*)key;   dst = (float4*)(g_Xr + XTOT); cnt = XTOT / 4; }
    else {
        int ws = sel - 2;
        src = (ws == 0) ? (const float4*)Wq : (ws == 1) ? (const float4*)Wk : (const float4*)Wv;
        dst = (float4*)(g_Wr + (size_t)ws * DMODEL * DMODEL);
        cnt = DMODEL * DMODEL / 4;
    }
    for (int i = blockIdx.x * blockDim.x + threadIdx.x; i < cnt; i += gridDim.x * blockDim.x) {
        float4 v = src[i];
        v.x = __uint_as_float(f2tf(v.x));
        v.y = __uint_as_float(f2tf(v.y));
        v.z = __uint_as_float(f2tf(v.z));
        v.w = __uint_as_float(f2tf(v.w));
        dst[i] = v;
    }
}

// ─────────────────────────── Projection GEMM (unchanged from R14) ───────────
#define PJ_PITCH 36
#define PJ_SLABF (128 * PJ_PITCH)
#define PJ_SMEM  (4 * PJ_SLABF * 4)          // 73728 bytes: X0|W0|X1|W1

DINL void pj_stage(uint32_t smu, const float* X, const float* W,
                   int m0, int c0, int s, int b, int tid)
{
    uint32_t xo = smu + (uint32_t)(2 * b * PJ_SLABF) * 4;
    uint32_t wo = xo + (uint32_t)PJ_SLABF * 4;
    #pragma unroll
    for (int it = 0; it < 4; ++it) {
        int idx = it * 256 + tid;
        int r = idx >> 3, c4 = (idx & 7) * 4;
        cp16(xo + (uint32_t)(r * PJ_PITCH + c4) * 4,
             X + (size_t)(m0 + r) * DMODEL + s * 32 + c4);
        cp16(wo + (uint32_t)(r * PJ_PITCH + c4) * 4,
             W + (size_t)(c0 + r) * DMODEL + s * 32 + c4);
    }
}

__global__ __launch_bounds__(256, 2) void proj_tc(
    const float* __restrict__ coeff, const float* __restrict__ pw, const float* __restrict__ pb)
{
    extern __shared__ float sm[];

    int tid = threadIdx.x, wid = tid >> 5, lane = tid & 31;
    int warpM = wid >> 1, warpN = wid & 1;
    int g = lane >> 2, t = lane & 3;
    int mode = blockIdx.z;
    const float* X = g_Xr + (mode == 0 ? 0 : XTOT);
    const float* W = g_Wr + (size_t)mode * DMODEL * DMODEL;
    int m0 = blockIdx.x * 128;
    int c0 = blockIdx.y * 128;
    uint32_t smu = smem_u32(sm);

    uint32_t xa_off = (uint32_t)((warpM * 32 + ldsm_a_row(lane)) * PJ_PITCH + ldsm_a_col(lane));
    uint32_t wb_off = (uint32_t)(PJ_SLABF + (warpN * 64 + ldsm_b_row(lane)) * PJ_PITCH + ldsm_b_col(lane));

    float acc[2][8][4];
    #pragma unroll
    for (int mb = 0; mb < 2; ++mb)
        #pragma unroll
        for (int nb = 0; nb < 8; ++nb)
            #pragma unroll
            for (int r = 0; r < 4; ++r) acc[mb][nb][r] = 0.f;

    pj_stage(smu, X, W, m0, c0, 0, 0, tid);
    CP_COMMIT();

    for (int s = 0; s < 16; ++s) {
        int cur = s & 1;
        if (s < 15) {
            pj_stage(smu, X, W, m0, c0, s + 1, cur ^ 1, tid);
            CP_COMMIT();
            CP_WAIT(1);
        } else {
            CP_WAIT(0);
        }
        __syncthreads();

        uint32_t buf = smu + (uint32_t)(2 * cur * PJ_SLABF) * 4;
        uint32_t xa = buf + xa_off * 4;
        uint32_t wb = buf + wb_off * 4;

        #pragma unroll
        for (int ks = 0; ks < 4; ++ks) {
            int k = ks * 8;
            uint32_t af[2][4];
            ldsm4(af[0], xa + (uint32_t)k * 4);
            ldsm4(af[1], xa + (uint32_t)(16 * PJ_PITCH + k) * 4);
            uint32_t bf[4][4];
            #pragma unroll
            for (int p = 0; p < 4; ++p)
                ldsm4(bf[p], wb + (uint32_t)(p * 16 * PJ_PITCH + k) * 4);
            #pragma unroll
            for (int mb = 0; mb < 2; ++mb)
                #pragma unroll
                for (int p = 0; p < 4; ++p) {
                    mma8(acc[mb][2 * p],     af[mb], &bf[p][0]);
                    mma8(acc[mb][2 * p + 1], af[mb], &bf[p][2]);
                }
        }
        __syncthreads();
    }

    #pragma unroll
    for (int mb = 0; mb < 2; ++mb) {
        #pragma unroll
        for (int nb = 0; nb < 8; ++nb) {
            #pragma unroll
            for (int r = 0; r < 4; ++r) {
                int row = warpM * 32 + mb * 16 + g + (r >> 1) * 8;
                int col = warpN * 64 + nb * 8 + 2 * t + (r & 1);
                int m = m0 + row;
                int n = m >> 11, l = m & (SEQL - 1);
                int c = c0 + col;
                int h = c >> 6, dd = c & 63;
                float x = acc[mb][nb][r];
                if (mode == 2) {
                    g_Vt[((size_t)((n * NHEAD + h) * HDIM + dd)) * SEQL + l] =
                        __uint_as_float(f2tf(x));
                } else {
                    size_t base = ((size_t)(n * NHEAD + h) * SEQL + l) * CATD;
                    float w = pw[c];
                    float sn, cs;
                    if (mode == 0) {
                        float sp = softplus_f(x);
                        sincos_red((float)l * w + pb[c], &sn, &cs);
                        g_A[base + dd]      = __uint_as_float(f2tf(sp * cs));
                        g_A[base + 64 + dd] = __uint_as_float(f2tf(sp * sn));
                    } else {
                        float sp = softplus_f(x) * coeff[c];
                        sincos_red((float)l * w, &sn, &cs);
                        g_B[base + dd]      = __uint_as_float(f2tf(sp * cs));
                        g_B[base + 64 + dd] = __uint_as_float(f2tf(sp * sn));
                    }
                }
            }
        }
    }
}

// ─────────────────────────── Attention (warp-pair key-split, 16 warps/SM) ───
// 256 threads / 8 warps per CTA; CTA = (nh, 64 q rows). Warp pair pj owns
// 16 q-rows; the pair's two warps split each 64-key chunk (32 keys each).
// A resident in smem (a-frags re-ldsm'd per k-step -> low regs). S warp-private.
// Final O/asum pair-reduced through smem once. 101KB smem -> 2 CTAs/SM.
#define AP 132
#define VP 68
#define SP 36
#define A_F   0
#define B_F   (64 * AP)                      // 8448
#define V_F   (2 * 64 * AP)                  // 16896
#define S_F   (2 * 64 * AP + 64 * VP)        // 21248
#define AT_SMEM ((S_F + 8 * 16 * SP) * 4)    // 103424 bytes

__global__ __launch_bounds__(256, 2) void attn_tc(float* __restrict__ out)
{
    extern __shared__ float sm[];

    int tid = threadIdx.x, wid = tid >> 5, lane = tid & 31;
    int g = lane >> 2, t = lane & 3;
    int half = wid & 1;              // key half: 0 -> keys [0,32), 1 -> [32,64)
    int pj = wid >> 1;               // pair id: q-rows [16*pj, 16*pj+16)
    int wr = pj * 16;

    int nh = blockIdx.y;
    int n = nh >> 3, h = nh & 7;
    int qt = (int)gridDim.x - 1 - (int)blockIdx.x;      // heavy tiles first
    int q0 = qt * 64;

    const float* Ab = g_A  + (size_t)nh * SEQL * CATD;
    const float* Bb = g_B  + (size_t)nh * SEQL * CATD;
    const float* Vb = g_Vt + (size_t)nh * HDIM * SEQL;

    uint32_t smu = smem_u32(sm);

    // per-lane ldmatrix bases
    uint32_t aA = smu + (uint32_t)(A_F + (wr + ldsm_a_row(lane)) * AP + ldsm_a_col(lane)) * 4;
    uint32_t bB = smu + (uint32_t)(B_F + (half * 32 + ldsm_b_row(lane)) * AP + ldsm_b_col(lane)) * 4;
    uint32_t vB = smu + (uint32_t)(V_F + ldsm_b_row(lane) * VP + half * 32 + ldsm_b_col(lane)) * 4;
    uint32_t sA = smu + (uint32_t)(S_F + wid * 16 * SP + ldsm_a_row(lane) * SP + ldsm_a_col(lane)) * 4;
    float (*Ssw)[SP] = (float(*)[SP])(sm + S_F + wid * 16 * SP);

    // ── one-time: stage A tile (64x128) resident into A region ──
    #pragma unroll
    for (int it = 0; it < 8; ++it) {
        int idx = it * 256 + tid;
        int r = idx >> 5, c4 = (idx & 31) * 4;
        cp16(smu + (uint32_t)(A_F + r * AP + c4) * 4, Ab + (size_t)(q0 + r) * CATD + c4);
    }
    CP_WAIT0();

    float O[8][4];
    #pragma unroll
    for (int nb = 0; nb < 8; ++nb)
        #pragma unroll
        for (int r = 0; r < 4; ++r) O[nb][r] = 0.f;
    float asum[2] = {0.f, 0.f};

    for (int kt = 0; kt <= qt; ++kt) {
        int k0 = kt * 64;
        __syncthreads();   // prev chunk's mma1/mma2 done with Bs/Vs (A stores on iter 0)

        // ── stage B chunk (64x128) + V chunk (64x64) via cp.async ──
        #pragma unroll
        for (int it = 0; it < 8; ++it) {
            int idx = it * 256 + tid;
            int r = idx >> 5, c4 = (idx & 31) * 4;
            cp16(smu + (uint32_t)(B_F + r * AP + c4) * 4, Bb + (size_t)(k0 + r) * CATD + c4);
        }
        #pragma unroll
        for (int it = 0; it < 4; ++it) {
            int idx = it * 256 + tid;
            int r = idx >> 4, c4 = (idx & 15) * 4;
            cp16(smu + (uint32_t)(V_F + r * VP + c4) * 4, Vb + (size_t)r * SEQL + k0 + c4);
        }
        CP_WAIT0();
        __syncthreads();

        bool diag = (kt == qt);
        // fully-masked chunk for this warp? (diag, odd half above all pair rows)
        if (diag && half * 32 > wr + 15) continue;   // no CTA barriers skipped

        // ── mma1: S(16x32) = A(16x128) · B_half^T (a-frags re-ldsm'd per ks) ──
        float S[4][4];
        #pragma unroll
        for (int nb = 0; nb < 4; ++nb)
            #pragma unroll
            for (int r = 0; r < 4; ++r) S[nb][r] = 0.f;

        #pragma unroll 4
        for (int ks = 0; ks < 16; ++ks) {
            int k = ks * 8;
            uint32_t a[4];
            ldsm4(a, aA + (uint32_t)k * 4);
            uint32_t bf0[4], bf1[4];
            ldsm4(bf0, bB + (uint32_t)k * 4);
            ldsm4(bf1, bB + (uint32_t)(16 * AP + k) * 4);
            mma8(S[0], a, &bf0[0]);
            mma8(S[1], a, &bf0[2]);
            mma8(S[2], a, &bf1[0]);
            mma8(S[3], a, &bf1[2]);
        }

        // ── epilogue: mask + |S| accumulation + S (tf32) into warp-private Ssw ──
        #pragma unroll
        for (int nb = 0; nb < 4; ++nb) {
            int col = nb * 8 + 2 * t;                   // col within warp's 32 keys
            int kl = half * 32 + col;                   // key local to chunk
            #pragma unroll
            for (int rh = 0; rh < 2; ++rh) {
                int rowl = g + rh * 8;                  // row within warp tile
                float v0 = S[nb][rh * 2 + 0];
                float v1 = S[nb][rh * 2 + 1];
                if (diag) {
                    int qg = wr + rowl;                 // q local to tile (k0 == q0)
                    if (kl + 0 > qg) v0 = 0.f;
                    if (kl + 1 > qg) v1 = 0.f;
                }
                asum[rh] += fabsf(v0) + fabsf(v1);
                float2 st;
                st.x = __uint_as_float(f2tf(v0));
                st.y = __uint_as_float(f2tf(v1));
                *(float2*)&Ssw[rowl][col] = st;
            }
        }
        __syncwarp();

        // ── mma2: O(16x64) += S(16x32) · Vt_half^T ──
        #pragma unroll
        for (int ks = 0; ks < 4; ++ks) {
            int k = ks * 8;
            uint32_t a2[4];
            ldsm4(a2, sA + (uint32_t)k * 4);
            uint32_t bf[4][4];
            #pragma unroll
            for (int p = 0; p < 4; ++p)
                ldsm4(bf[p], vB + (uint32_t)(p * 16 * VP + k) * 4);
            #pragma unroll
            for (int p = 0; p < 4; ++p) {
                mma8(O[2 * p],     a2, &bf[p][0]);
                mma8(O[2 * p + 1], a2, &bf[p][2]);
            }
        }
    }

    // ── quad-reduce asum across t lanes ──
    #pragma unroll
    for (int rh = 0; rh < 2; ++rh) {
        asum[rh] += __shfl_xor_sync(0xffffffffu, asum[rh], 1);
        asum[rh] += __shfl_xor_sync(0xffffffffu, asum[rh], 2);
    }

    // ── pair reduction of O and asum through smem (reuses B/V regions) ──
    __syncthreads();          // all warps done with Bs/Vs
    if (half == 1) {
        float* ob = sm + B_F + pj * 1024 + lane * 32;
        #pragma unroll
        for (int nb = 0; nb < 8; ++nb)
            #pragma unroll
            for (int r = 0; r < 4; ++r) ob[nb * 4 + r] = O[nb][r];
        if (t == 0) {
            sm[V_F + pj * 16 + g]     = asum[0];
            sm[V_F + pj * 16 + g + 8] = asum[1];
        }
    }
    __syncthreads();
    if (half == 0) {
        const float* ob = sm + B_F + pj * 1024 + lane * 32;
        #pragma unroll
        for (int nb = 0; nb < 8; ++nb)
            #pragma unroll
            for (int r = 0; r < 4; ++r) O[nb][r] += ob[nb * 4 + r];
        asum[0] += sm[V_F + pj * 16 + g];
        asum[1] += sm[V_F + pj * 16 + g + 8];

        #pragma unroll
        for (int rh = 0; rh < 2; ++rh) {
            float inv = 1.f / asum[rh];
            int l = q0 + wr + g + rh * 8;
            float* op = out + ((size_t)(n * SEQL + l)) * DMODEL + h * HDIM;
            #pragma unroll
            for (int nb = 0; nb < 8; ++nb) {
                int col = nb * 8 + 2 * t;
                float2 st;
                st.x = O[nb][rh * 2 + 0] * inv;
                st.y = O[nb][rh * 2 + 1] * inv;
                *(float2*)(op + col) = st;
            }
        }
    }
}

// ─────────────────────────── launch ─────────────────────────────────────────
extern "C" void kernel_launch(void* const* d_in, const int* in_sizes, int n_in,
                              void* d_out, int out_size)
{
    const float* query = (const float*)d_in[0];
    const float* key   = (const float*)d_in[1];
    const float* Wq    = (const float*)d_in[2];
    const float* Wk    = (const float*)d_in[3];
    const float* Wv    = (const float*)d_in[4];
    const float* coeff = (const float*)d_in[5];
    const float* pw    = (const float*)d_in[6];
    const float* pb    = (const float*)d_in[7];
    float* out = (float*)d_out;

    cudaFuncSetAttribute(proj_tc, cudaFuncAttributeMaxDynamicSharedMemorySize, PJ_SMEM);
    cudaFuncSetAttribute(attn_tc, cudaFuncAttributeMaxDynamicSharedMemorySize, AT_SMEM);

    prepass_tc<<<dim3(256, 5), 256>>>(query, key, Wq, Wk, Wv);
    proj_tc<<<dim3(32, 4, 3), 256, PJ_SMEM>>>(coeff, pw, pb);
    attn_tc<<<dim3(32, 16), 256, AT_SMEM>>>(out);
}